// round 1
// baseline (speedup 1.0000x reference)
#include <cuda_runtime.h>
#include <math.h>

#define M_ROWS 512
#define K_COMP 8
#define D_DIM  4
#define B_PTS  4096
#define PHI_DIM 120
#define Z_COLS 80
#define LOG2PI_F 1.8378770664093453f

// Scratch (device globals — no allocation allowed)
__device__ float g_params[M_ROWS * 120];  // per (m,k): mu[4], L10,L20,L21,L30,L31,L32, r0..r3, ck  (15 floats)
__device__ float g_z[M_ROWS * Z_COLS];

// ---------------------------------------------------------------------------
// Kernel 1: per-m preprocessing (one thread per m)
// ---------------------------------------------------------------------------
__global__ void gmm_prep(const float* __restrict__ phi) {
    int m = blockIdx.x * blockDim.x + threadIdx.x;
    if (m >= M_ROWS) return;
    const float* pm = phi + m * PHI_DIM;

    // softmax over pi_tilde (K=8)
    float pt[K_COMP];
    float mx = -INFINITY;
    #pragma unroll
    for (int k = 0; k < K_COMP; k++) { pt[k] = pm[k]; mx = fmaxf(mx, pt[k]); }
    float e[K_COMP]; float s = 0.f;
    #pragma unroll
    for (int k = 0; k < K_COMP; k++) { e[k] = expf(pt[k] - mx); s += e[k]; }
    float inv_s = 1.0f / s;

    float* Z = g_z + m * Z_COLS;
    float* P = g_params + m * 120;

    #pragma unroll
    for (int k = 0; k < K_COMP; k++) {
        float pik = e[k] * inv_s;
        Z[64 + k] = pik;

        // mu
        #pragma unroll
        for (int d = 0; d < D_DIM; d++) {
            float mud = pm[8 + k * 4 + d];
            P[k * 15 + d] = mud;
            Z[k * 4 + d] = mud;
        }

        // L lower-tri vec: L00,L10,L11,L20,L21,L22,L30,L31,L32,L33
        const float* lv = pm + 40 + k * 10;
        float L00 = lv[0], L10 = lv[1], L11 = lv[2], L20 = lv[3], L21 = lv[4];
        float L22 = lv[5], L30 = lv[6], L31 = lv[7], L32 = lv[8], L33 = lv[9];

        P[k * 15 + 4] = L10;
        P[k * 15 + 5] = L20;
        P[k * 15 + 6] = L21;
        P[k * 15 + 7] = L30;
        P[k * 15 + 8] = L31;
        P[k * 15 + 9] = L32;
        P[k * 15 + 10] = 1.0f / L00;
        P[k * 15 + 11] = 1.0f / L11;
        P[k * 15 + 12] = 1.0f / L22;
        P[k * 15 + 13] = 1.0f / L33;

        float log_det = 2.0f * (logf(fmaxf(fabsf(L00), 1e-8f)) +
                                logf(fmaxf(fabsf(L11), 1e-8f)) +
                                logf(fmaxf(fabsf(L22), 1e-8f)) +
                                logf(fmaxf(fabsf(L33), 1e-8f)));
        // ck = log(clip(pi)) - 0.5*(D*log(2pi) + log_det)
        P[k * 15 + 14] = logf(fmaxf(pik, 1e-8f)) - 0.5f * (4.0f * LOG2PI_F + log_det);

        // z log_L columns (clip 1e-6 here, per reference)
        Z[32 + k * 4 + 0] = logf(fmaxf(fabsf(L00), 1e-6f));
        Z[32 + k * 4 + 1] = logf(fmaxf(fabsf(L11), 1e-6f));
        Z[32 + k * 4 + 2] = logf(fmaxf(fabsf(L22), 1e-6f));
        Z[32 + k * 4 + 3] = logf(fmaxf(fabsf(L33), 1e-6f));
    }
}

// ---------------------------------------------------------------------------
// Kernel 2: main responsibility accumulation. One block per m.
// ---------------------------------------------------------------------------
__global__ void __launch_bounds__(256, 1) gmm_main(const float4* __restrict__ X) {
    int m = blockIdx.x;
    const float* P = g_params + m * 120;

    // Load all per-(m,k) parameters into registers (fully unrolled)
    float mu0[K_COMP], mu1[K_COMP], mu2[K_COMP], mu3[K_COMP];
    float L10[K_COMP], L20[K_COMP], L21[K_COMP], L30[K_COMP], L31[K_COMP], L32[K_COMP];
    float r0[K_COMP], r1[K_COMP], r2[K_COMP], r3[K_COMP], ck[K_COMP];
    #pragma unroll
    for (int k = 0; k < K_COMP; k++) {
        const float* q = P + k * 15;
        mu0[k] = q[0];  mu1[k] = q[1];  mu2[k] = q[2];  mu3[k] = q[3];
        L10[k] = q[4];  L20[k] = q[5];  L21[k] = q[6];
        L30[k] = q[7];  L31[k] = q[8];  L32[k] = q[9];
        r0[k] = q[10];  r1[k] = q[11];  r2[k] = q[12];  r3[k] = q[13];
        ck[k] = q[14];
    }

    float acc[K_COMP];
    #pragma unroll
    for (int k = 0; k < K_COMP; k++) acc[k] = 0.f;

    for (int i = threadIdx.x; i < B_PTS; i += 256) {
        float4 x = X[i];
        float lj[K_COMP];
        #pragma unroll
        for (int k = 0; k < K_COMP; k++) {
            float d0 = x.x - mu0[k];
            float d1 = x.y - mu1[k];
            float d2 = x.z - mu2[k];
            float d3 = x.w - mu3[k];
            float a0 = d0 * r0[k];
            float a1 = (d1 - L10[k] * a0) * r1[k];
            float a2 = (d2 - L20[k] * a0 - L21[k] * a1) * r2[k];
            float a3 = (d3 - L30[k] * a0 - L31[k] * a1 - L32[k] * a2) * r3[k];
            float maha = a0 * a0 + a1 * a1 + a2 * a2 + a3 * a3;
            lj[k] = ck[k] - 0.5f * maha;
        }
        float mx = lj[0];
        #pragma unroll
        for (int k = 1; k < K_COMP; k++) mx = fmaxf(mx, lj[k]);
        float ex[K_COMP]; float s = 0.f;
        #pragma unroll
        for (int k = 0; k < K_COMP; k++) { ex[k] = __expf(lj[k] - mx); s += ex[k]; }
        float inv = __fdividef(1.0f, s);
        #pragma unroll
        for (int k = 0; k < K_COMP; k++) acc[k] += ex[k] * inv;
    }

    // block reduce 8 accumulators
    __shared__ float sred[8][K_COMP];
    unsigned wid = threadIdx.x >> 5, lane = threadIdx.x & 31;
    #pragma unroll
    for (int k = 0; k < K_COMP; k++) {
        float v = acc[k];
        v += __shfl_down_sync(0xffffffffu, v, 16);
        v += __shfl_down_sync(0xffffffffu, v, 8);
        v += __shfl_down_sync(0xffffffffu, v, 4);
        v += __shfl_down_sync(0xffffffffu, v, 2);
        v += __shfl_down_sync(0xffffffffu, v, 1);
        if (lane == 0) sred[wid][k] = v;
    }
    __syncthreads();
    if (threadIdx.x < K_COMP) {
        float v = 0.f;
        #pragma unroll
        for (int w = 0; w < 8; w++) v += sred[w][threadIdx.x];
        g_z[m * Z_COLS + 72 + threadIdx.x] = v * (1.0f / (float)B_PTS);
    }
}

// ---------------------------------------------------------------------------
// Kernel 3: column-wise standardization (80 columns, 512 rows)
// ---------------------------------------------------------------------------
__global__ void gmm_norm(float* __restrict__ out) {
    int c = blockIdx.x;        // column
    int t = threadIdx.x;       // row (512 threads)
    float v = g_z[t * Z_COLS + c];

    __shared__ float sh[16];
    __shared__ float s_mean, s_rstd;
    unsigned wid = t >> 5, lane = t & 31;

    // pass 1: mean
    float s = v;
    s += __shfl_down_sync(0xffffffffu, s, 16);
    s += __shfl_down_sync(0xffffffffu, s, 8);
    s += __shfl_down_sync(0xffffffffu, s, 4);
    s += __shfl_down_sync(0xffffffffu, s, 2);
    s += __shfl_down_sync(0xffffffffu, s, 1);
    if (lane == 0) sh[wid] = s;
    __syncthreads();
    if (wid == 0) {
        float w = (lane < 16) ? sh[lane] : 0.f;
        w += __shfl_down_sync(0xffffffffu, w, 8);
        w += __shfl_down_sync(0xffffffffu, w, 4);
        w += __shfl_down_sync(0xffffffffu, w, 2);
        w += __shfl_down_sync(0xffffffffu, w, 1);
        if (lane == 0) s_mean = w * (1.0f / (float)M_ROWS);
    }
    __syncthreads();
    float mean = s_mean;
    float d = v - mean;

    // pass 2: variance (ddof=1)
    float q = d * d;
    q += __shfl_down_sync(0xffffffffu, q, 16);
    q += __shfl_down_sync(0xffffffffu, q, 8);
    q += __shfl_down_sync(0xffffffffu, q, 4);
    q += __shfl_down_sync(0xffffffffu, q, 2);
    q += __shfl_down_sync(0xffffffffu, q, 1);
    __syncthreads();  // protect sh reuse
    if (lane == 0) sh[wid] = q;
    __syncthreads();
    if (wid == 0) {
        float w = (lane < 16) ? sh[lane] : 0.f;
        w += __shfl_down_sync(0xffffffffu, w, 8);
        w += __shfl_down_sync(0xffffffffu, w, 4);
        w += __shfl_down_sync(0xffffffffu, w, 2);
        w += __shfl_down_sync(0xffffffffu, w, 1);
        if (lane == 0) {
            float var = w * (1.0f / (float)(M_ROWS - 1));
            s_rstd = 1.0f / fmaxf(sqrtf(var), 1e-6f);
        }
    }
    __syncthreads();
    out[t * Z_COLS + c] = d * s_rstd;
}

// ---------------------------------------------------------------------------
extern "C" void kernel_launch(void* const* d_in, const int* in_sizes, int n_in,
                              void* d_out, int out_size) {
    const float* phi = (const float*)d_in[0];
    const float4* X = (const float4*)d_in[1];
    float* out = (float*)d_out;

    gmm_prep<<<2, 256>>>(phi);
    gmm_main<<<M_ROWS, 256>>>(X);
    gmm_norm<<<Z_COLS, M_ROWS>>>(out);
}

// round 2
// speedup vs baseline: 2.0914x; 2.0914x over previous
#include <cuda_runtime.h>
#include <math.h>

#define M_ROWS 512
#define K_COMP 8
#define B_PTS  4096
#define B_HALF 2048
#define PHI_DIM 120
#define Z_COLS 80
#define LOG2PI_F 1.8378770664093453f
#define RSQRT2_F 0.70710678118654752f

// Scratch (device globals — no allocation allowed)
__device__ float g_z[M_ROWS * Z_COLS];          // columns 0..71 (mu, logL, pi)
__device__ float g_resp[2][M_ROWS][K_COMP];     // partial resp sums per half

// ---------------------------------------------------------------------------
// Main kernel: fused prep + responsibility accumulation.
// grid = 1024: block bx -> m = bx>>1, half = bx&1. 128 threads.
// ---------------------------------------------------------------------------
__global__ void __launch_bounds__(128, 3) gmm_main(const float* __restrict__ phi,
                                                   const float4* __restrict__ X) {
    const int m = blockIdx.x >> 1;
    const int half = blockIdx.x & 1;
    const int tid = threadIdx.x;

    // Param layout per k: rs0,rs1,rs2,rs3, c0,c1,c2,c3, s10,s20,s21,s30,s31,s32, ck
    __shared__ float sp[K_COMP][15];

    // ---- fused prep: threads 0..7, one k each ----
    if (tid < K_COMP) {
        const int k = tid;
        const float* pm = phi + m * PHI_DIM;

        // softmax over pi_tilde (redundant per-thread, trivial cost)
        float mx = -INFINITY;
        #pragma unroll
        for (int j = 0; j < K_COMP; j++) mx = fmaxf(mx, pm[j]);
        float s = 0.f;
        #pragma unroll
        for (int j = 0; j < K_COMP; j++) s += __expf(pm[j] - mx);
        float pik = __expf(pm[k] - mx) / s;

        float mu0 = pm[8 + k * 4 + 0];
        float mu1 = pm[8 + k * 4 + 1];
        float mu2 = pm[8 + k * 4 + 2];
        float mu3 = pm[8 + k * 4 + 3];

        const float* lv = pm + 40 + k * 10;
        float L00 = lv[0], L10 = lv[1], L11 = lv[2], L20 = lv[3], L21 = lv[4];
        float L22 = lv[5], L30 = lv[6], L31 = lv[7], L32 = lv[8], L33 = lv[9];

        float r0 = 1.0f / L00, r1 = 1.0f / L11, r2 = 1.0f / L22, r3 = 1.0f / L33;
        float rs0 = r0 * RSQRT2_F, rs1 = r1 * RSQRT2_F;
        float rs2 = r2 * RSQRT2_F, rs3 = r3 * RSQRT2_F;

        sp[k][0] = rs0;  sp[k][1] = rs1;  sp[k][2] = rs2;  sp[k][3] = rs3;
        sp[k][4] = -mu0 * rs0;
        sp[k][5] = -mu1 * rs1;
        sp[k][6] = -mu2 * rs2;
        sp[k][7] = -mu3 * rs3;
        sp[k][8]  = L10 * r1;
        sp[k][9]  = L20 * r2;
        sp[k][10] = L21 * r2;
        sp[k][11] = L30 * r3;
        sp[k][12] = L31 * r3;
        sp[k][13] = L32 * r3;

        float ld0 = __logf(fmaxf(fabsf(L00), 1e-8f));
        float ld1 = __logf(fmaxf(fabsf(L11), 1e-8f));
        float ld2 = __logf(fmaxf(fabsf(L22), 1e-8f));
        float ld3 = __logf(fmaxf(fabsf(L33), 1e-8f));
        float log_det = 2.0f * (ld0 + ld1 + ld2 + ld3);
        sp[k][14] = __logf(fmaxf(pik, 1e-8f)) - 0.5f * (4.0f * LOG2PI_F + log_det);

        if (half == 0) {
            float* Z = g_z + m * Z_COLS;
            Z[k * 4 + 0] = mu0;  Z[k * 4 + 1] = mu1;
            Z[k * 4 + 2] = mu2;  Z[k * 4 + 3] = mu3;
            Z[32 + k * 4 + 0] = __logf(fmaxf(fabsf(L00), 1e-6f));
            Z[32 + k * 4 + 1] = __logf(fmaxf(fabsf(L11), 1e-6f));
            Z[32 + k * 4 + 2] = __logf(fmaxf(fabsf(L22), 1e-6f));
            Z[32 + k * 4 + 3] = __logf(fmaxf(fabsf(L33), 1e-6f));
            Z[64 + k] = pik;
        }
    }
    __syncthreads();

    // ---- cache params in registers (broadcast LDS, conflict-free) ----
    float rs0[K_COMP], rs1[K_COMP], rs2[K_COMP], rs3[K_COMP];
    float c0[K_COMP], c1[K_COMP], c2[K_COMP], c3[K_COMP];
    float s10[K_COMP], s20[K_COMP], s21[K_COMP];
    float s30[K_COMP], s31[K_COMP], s32[K_COMP], ck[K_COMP];
    #pragma unroll
    for (int k = 0; k < K_COMP; k++) {
        rs0[k] = sp[k][0];  rs1[k] = sp[k][1];  rs2[k] = sp[k][2];  rs3[k] = sp[k][3];
        c0[k]  = sp[k][4];  c1[k]  = sp[k][5];  c2[k]  = sp[k][6];  c3[k]  = sp[k][7];
        s10[k] = sp[k][8];  s20[k] = sp[k][9];  s21[k] = sp[k][10];
        s30[k] = sp[k][11]; s31[k] = sp[k][12]; s32[k] = sp[k][13];
        ck[k]  = sp[k][14];
    }

    float acc[K_COMP];
    #pragma unroll
    for (int k = 0; k < K_COMP; k++) acc[k] = 0.f;

    const int i0 = half * B_HALF;
    for (int i = i0 + tid; i < i0 + B_HALF; i += 128) {
        float4 x = X[i];
        float lj[K_COMP];
        #pragma unroll
        for (int k = 0; k < K_COMP; k++) {
            float a0 = __fmaf_rn(x.x, rs0[k], c0[k]);
            float a1 = __fmaf_rn(x.y, rs1[k], c1[k]) - s10[k] * a0;
            float a2 = __fmaf_rn(x.z, rs2[k], c2[k]) - s20[k] * a0 - s21[k] * a1;
            float a3 = __fmaf_rn(x.w, rs3[k], c3[k]) - s30[k] * a0 - s31[k] * a1 - s32[k] * a2;
            lj[k] = ck[k] - a0 * a0 - a1 * a1 - a2 * a2 - a3 * a3;
        }
        float mx = lj[0];
        #pragma unroll
        for (int k = 1; k < K_COMP; k++) mx = fmaxf(mx, lj[k]);
        float ex[K_COMP]; float s = 0.f;
        #pragma unroll
        for (int k = 0; k < K_COMP; k++) { ex[k] = __expf(lj[k] - mx); s += ex[k]; }
        float inv = __fdividef(1.0f, s);
        #pragma unroll
        for (int k = 0; k < K_COMP; k++) acc[k] = __fmaf_rn(ex[k], inv, acc[k]);
    }

    // ---- block reduce 4 warps ----
    __shared__ float sred[4][K_COMP];
    unsigned wid = tid >> 5, lane = tid & 31;
    #pragma unroll
    for (int k = 0; k < K_COMP; k++) {
        float v = acc[k];
        v += __shfl_down_sync(0xffffffffu, v, 16);
        v += __shfl_down_sync(0xffffffffu, v, 8);
        v += __shfl_down_sync(0xffffffffu, v, 4);
        v += __shfl_down_sync(0xffffffffu, v, 2);
        v += __shfl_down_sync(0xffffffffu, v, 1);
        if (lane == 0) sred[wid][k] = v;
    }
    __syncthreads();
    if (tid < K_COMP) {
        float v = sred[0][tid] + sred[1][tid] + sred[2][tid] + sred[3][tid];
        g_resp[half][m][tid] = v;
    }
}

// ---------------------------------------------------------------------------
// Standardization: 80 blocks (one per column) x 512 threads (rows).
// ---------------------------------------------------------------------------
__global__ void gmm_norm(float* __restrict__ out) {
    int c = blockIdx.x;
    int t = threadIdx.x;

    float v;
    if (c < 72) {
        v = g_z[t * Z_COLS + c];
    } else {
        int k = c - 72;
        v = (g_resp[0][t][k] + g_resp[1][t][k]) * (1.0f / (float)B_PTS);
    }

    __shared__ float sh[16];
    __shared__ float s_mean, s_rstd;
    unsigned wid = t >> 5, lane = t & 31;

    float s = v;
    s += __shfl_down_sync(0xffffffffu, s, 16);
    s += __shfl_down_sync(0xffffffffu, s, 8);
    s += __shfl_down_sync(0xffffffffu, s, 4);
    s += __shfl_down_sync(0xffffffffu, s, 2);
    s += __shfl_down_sync(0xffffffffu, s, 1);
    if (lane == 0) sh[wid] = s;
    __syncthreads();
    if (wid == 0) {
        float w = (lane < 16) ? sh[lane] : 0.f;
        w += __shfl_down_sync(0xffffffffu, w, 8);
        w += __shfl_down_sync(0xffffffffu, w, 4);
        w += __shfl_down_sync(0xffffffffu, w, 2);
        w += __shfl_down_sync(0xffffffffu, w, 1);
        if (lane == 0) s_mean = w * (1.0f / (float)M_ROWS);
    }
    __syncthreads();
    float d = v - s_mean;

    float q = d * d;
    q += __shfl_down_sync(0xffffffffu, q, 16);
    q += __shfl_down_sync(0xffffffffu, q, 8);
    q += __shfl_down_sync(0xffffffffu, q, 4);
    q += __shfl_down_sync(0xffffffffu, q, 2);
    q += __shfl_down_sync(0xffffffffu, q, 1);
    __syncthreads();
    if (lane == 0) sh[wid] = q;
    __syncthreads();
    if (wid == 0) {
        float w = (lane < 16) ? sh[lane] : 0.f;
        w += __shfl_down_sync(0xffffffffu, w, 8);
        w += __shfl_down_sync(0xffffffffu, w, 4);
        w += __shfl_down_sync(0xffffffffu, w, 2);
        w += __shfl_down_sync(0xffffffffu, w, 1);
        if (lane == 0) {
            float var = w * (1.0f / (float)(M_ROWS - 1));
            s_rstd = 1.0f / fmaxf(sqrtf(var), 1e-6f);
        }
    }
    __syncthreads();
    out[t * Z_COLS + c] = d * s_rstd;
}

// ---------------------------------------------------------------------------
extern "C" void kernel_launch(void* const* d_in, const int* in_sizes, int n_in,
                              void* d_out, int out_size) {
    const float* phi = (const float*)d_in[0];
    const float4* X = (const float4*)d_in[1];
    float* out = (float*)d_out;

    gmm_main<<<M_ROWS * 2, 128>>>(phi, X);
    gmm_norm<<<Z_COLS, M_ROWS>>>(out);
}